// round 2
// baseline (speedup 1.0000x reference)
#include <cuda_runtime.h>
#include <math.h>

// Problem constants
#define BATCH 512
#define HDIM  64
#define EDIM  64
#define HPDIM 64
#define OBS   8
#define PRE   12
#define G3    192   // 3*H

// Scratch (device globals — no allocation allowed)
__device__ float g_h[BATCH * HDIM];        // GRU hidden state
__device__ float g_uT[HPDIM * BATCH];      // u transposed: [k][i],  u = pos @ W_rel
__device__ float g_hpart[BATCH * HDIM];    // h @ Wp2 + b_pool, per agent
__device__ float g_pooled[2 * BATCH * HDIM]; // two j-halves, maxed in update
__device__ float g_WihT[HDIM * G3];        // W_ih transposed [d][g]
__device__ float g_WhhT[HDIM * G3];        // W_hh transposed [d][g]

// ---------------------------------------------------------------------------
// Init: copy group_track into out, build uT from last obs pos, hpart from
// hidden_state, zero GRU h, transpose W_ih / W_hh.
// Grid: 704 blocks x 64 threads. Blocks [0,512): per-agent. [512,704): transpose.
// ---------------------------------------------------------------------------
__global__ void init_kernel(const float* __restrict__ hidden,
                            const float* __restrict__ gt,
                            const float* __restrict__ W_ih,
                            const float* __restrict__ W_hh,
                            const float* __restrict__ W_rel,
                            const float* __restrict__ W_pool,
                            const float* __restrict__ b_pool,
                            float* __restrict__ out)
{
    int bid = blockIdx.x;
    int c = threadIdx.x;
    if (bid < BATCH) {
        int i = bid;
        // copy observed track: out[i, 0:8, :]
        if (c < 2 * OBS) out[i * 2 * (OBS + PRE) + c] = gt[i * 2 * OBS + c];
        // uT[k][i] from last observed position
        float px = gt[i * 2 * OBS + 2 * (OBS - 1) + 0];
        float py = gt[i * 2 * OBS + 2 * (OBS - 1) + 1];
        g_uT[c * BATCH + i] = px * W_rel[c] + py * W_rel[HPDIM + c];
        // hpart[i][c] = sum_d hidden[i][d] * W_pool[64+d][c] + b_pool[c]
        float acc = b_pool[c];
        #pragma unroll 8
        for (int d = 0; d < HDIM; ++d)
            acc += hidden[i * HDIM + d] * W_pool[(HPDIM + d) * HDIM + c];
        g_hpart[i * HDIM + c] = acc;
        g_h[i * HDIM + c] = 0.0f;
    } else {
        int g = bid - BATCH;   // 0..191
        int d = c;             // 0..63
        g_WihT[d * G3 + g] = W_ih[g * HDIM + d];
        g_WhhT[d * G3 + g] = W_hh[g * HDIM + d];
    }
}

// ---------------------------------------------------------------------------
// Spool: for agent i (and one j-half), compute
//   pooled_half[i][c] = max_j relu( relu(u_j - u_i + b_rel) @ Wp1 + hpart_j )[c]
// NOTE orientation: rel[i,j] = pos_j - pos_i  =>  e = relu(u_j - u_i + b_rel).
// Grid: 1024 blocks (i = bid>>1, half = bid&1) x 256 threads (8 warps).
// Each warp handles 8 j's per 64-j tile; lane owns output cols (l, l+32).
// ---------------------------------------------------------------------------
__global__ void __launch_bounds__(256) spool_kernel(const float* __restrict__ W_pool,
                                                    const float* __restrict__ b_rel)
{
    __shared__ float a_s[HDIM];          // b_rel[k] - u_i[k]
    __shared__ float ws[HDIM * HDIM];    // Wp1 with (c, c+32) pair-interleave
    __shared__ float e_s[8][HDIM][8];    // per-warp e tiles, transposed [k][jj]
    __shared__ float red_s[8][HDIM];     // cross-warp max reduction

    int i    = blockIdx.x >> 1;
    int half = blockIdx.x & 1;
    int t = threadIdx.x;
    int w = t >> 5, l = t & 31;

    if (t < HDIM) a_s[t] = b_rel[t] - g_uT[t * BATCH + i];
    // Wp1 = W_pool rows [0,64). Interleave so (c, c+32) are adjacent for LDS.64.
    for (int idx = t; idx < HDIM * HDIM; idx += 256) {
        int k = idx >> 6, c = idx & 63;
        ws[k * 64 + ((c & 31) << 1) + (c >> 5)] = W_pool[k * HDIM + c];
    }
    __syncthreads();

    int jj   = l & 7;
    int koff = l >> 3;
    float mx0 = 0.0f, mx1 = 0.0f;   // relu => max starts at 0

    for (int tile = 0; tile < 4; ++tile) {
        int jbase = half * 256 + tile * 64 + w * 8;
        // Phase 1: e[k][jj] = relu(u_j[k] + (b_rel[k] - u_i[k])), k-major uT (coalesced)
        #pragma unroll
        for (int kk = 0; kk < 16; ++kk) {
            int k = kk * 4 + koff;
            float e = g_uT[k * BATCH + jbase + jj] + a_s[k];
            e_s[w][k][jj] = fmaxf(e, 0.0f);
        }
        __syncwarp();
        // Phase 2: 8 j x 2 c accumulators, init with hpart_j
        float acc[8][2];
        #pragma unroll
        for (int q = 0; q < 8; ++q) {
            acc[q][0] = g_hpart[(jbase + q) * HDIM + l];
            acc[q][1] = g_hpart[(jbase + q) * HDIM + l + 32];
        }
        #pragma unroll 16
        for (int k = 0; k < HDIM; ++k) {
            float2 wv = *(const float2*)&ws[k * 64 + 2 * l];
            float4 ea = *(const float4*)&e_s[w][k][0];
            float4 eb = *(const float4*)&e_s[w][k][4];
            acc[0][0] += ea.x * wv.x;  acc[0][1] += ea.x * wv.y;
            acc[1][0] += ea.y * wv.x;  acc[1][1] += ea.y * wv.y;
            acc[2][0] += ea.z * wv.x;  acc[2][1] += ea.z * wv.y;
            acc[3][0] += ea.w * wv.x;  acc[3][1] += ea.w * wv.y;
            acc[4][0] += eb.x * wv.x;  acc[4][1] += eb.x * wv.y;
            acc[5][0] += eb.y * wv.x;  acc[5][1] += eb.y * wv.y;
            acc[6][0] += eb.z * wv.x;  acc[6][1] += eb.z * wv.y;
            acc[7][0] += eb.w * wv.x;  acc[7][1] += eb.w * wv.y;
        }
        #pragma unroll
        for (int q = 0; q < 8; ++q) {
            mx0 = fmaxf(mx0, acc[q][0]);
            mx1 = fmaxf(mx1, acc[q][1]);
        }
        __syncwarp();
    }

    red_s[w][l] = mx0;
    red_s[w][l + 32] = mx1;
    __syncthreads();
    if (t < HDIM) {
        float m = red_s[0][t];
        #pragma unroll
        for (int q = 1; q < 8; ++q) m = fmaxf(m, red_s[q][t]);
        g_pooled[(half * BATCH + i) * HDIM + t] = m;
    }
}

// ---------------------------------------------------------------------------
// Update: pooled -> pos -> emb -> GRU(h) ; write pos to out; produce next
// step's uT (from pos) and hpart (from new h).
// Grid: 64 blocks x 256 threads; warp w handles agent a = bid*8 + w.
// ---------------------------------------------------------------------------
__global__ void __launch_bounds__(256) update_kernel(
    const float* __restrict__ W_emb, const float* __restrict__ b_emb,
    const float* __restrict__ b_ih,  const float* __restrict__ b_hh,
    const float* __restrict__ W_pos, const float* __restrict__ b_pos,
    const float* __restrict__ W_rel, const float* __restrict__ W_pool,
    const float* __restrict__ b_pool, float* __restrict__ out, int step)
{
    __shared__ float emb_s[8][HDIM];
    __shared__ float h_s[8][HDIM];
    __shared__ float hn_s[8][HDIM];

    int w = threadIdx.x >> 5, l = threadIdx.x & 31;
    int a = blockIdx.x * 8 + w;

    // pooled = max over the two spool halves
    float p0 = fmaxf(g_pooled[a * HDIM + l],
                     g_pooled[(BATCH + a) * HDIM + l]);
    float p1 = fmaxf(g_pooled[a * HDIM + l + 32],
                     g_pooled[(BATCH + a) * HDIM + l + 32]);

    // pos = pooled @ W_pos + b_pos  (warp butterfly reduction)
    float px = p0 * W_pos[l * 2 + 0] + p1 * W_pos[(l + 32) * 2 + 0];
    float py = p0 * W_pos[l * 2 + 1] + p1 * W_pos[(l + 32) * 2 + 1];
    #pragma unroll
    for (int s = 16; s; s >>= 1) {
        px += __shfl_xor_sync(0xffffffffu, px, s);
        py += __shfl_xor_sync(0xffffffffu, py, s);
    }
    px += b_pos[0]; py += b_pos[1];

    if (l == 0) {
        out[a * 2 * (OBS + PRE) + (OBS + step) * 2 + 0] = px;
        out[a * 2 * (OBS + PRE) + (OBS + step) * 2 + 1] = py;
    }

    // next-step uT
    g_uT[l * BATCH + a]        = px * W_rel[l]      + py * W_rel[HPDIM + l];
    g_uT[(l + 32) * BATCH + a] = px * W_rel[l + 32] + py * W_rel[HPDIM + l + 32];

    // emb = pos @ W_emb + b_emb ; stage h
    emb_s[w][l]      = px * W_emb[l]      + py * W_emb[EDIM + l]      + b_emb[l];
    emb_s[w][l + 32] = px * W_emb[l + 32] + py * W_emb[EDIM + l + 32] + b_emb[l + 32];
    float h0 = g_h[a * HDIM + l];
    float h1 = g_h[a * HDIM + l + 32];
    h_s[w][l] = h0; h_s[w][l + 32] = h1;
    __syncwarp();

    // GRU gates for columns c = l, l+32
    float hn[2];
    #pragma unroll
    for (int cc = 0; cc < 2; ++cc) {
        int c = l + cc * 32;
        float gir = b_ih[c], giz = b_ih[64 + c], gin = b_ih[128 + c];
        float ghr = b_hh[c], ghz = b_hh[64 + c], ghn = b_hh[128 + c];
        #pragma unroll 8
        for (int d = 0; d < HDIM; ++d) {
            float ed = emb_s[w][d], hd = h_s[w][d];
            gir += ed * g_WihT[d * G3 + c];
            giz += ed * g_WihT[d * G3 + 64 + c];
            gin += ed * g_WihT[d * G3 + 128 + c];
            ghr += hd * g_WhhT[d * G3 + c];
            ghz += hd * g_WhhT[d * G3 + 64 + c];
            ghn += hd * g_WhhT[d * G3 + 128 + c];
        }
        float r = 1.0f / (1.0f + expf(-(gir + ghr)));
        float z = 1.0f / (1.0f + expf(-(giz + ghz)));
        float n = tanhf(gin + r * ghn);
        float ho = cc ? h1 : h0;
        hn[cc] = (1.0f - z) * n + z * ho;
    }
    g_h[a * HDIM + l]      = hn[0];
    g_h[a * HDIM + l + 32] = hn[1];
    hn_s[w][l] = hn[0]; hn_s[w][l + 32] = hn[1];
    __syncwarp();

    // next-step hpart = h_new @ Wp2 + b_pool
    #pragma unroll
    for (int cc = 0; cc < 2; ++cc) {
        int c = l + cc * 32;
        float hp = b_pool[c];
        #pragma unroll 8
        for (int d = 0; d < HDIM; ++d)
            hp += hn_s[w][d] * W_pool[(HPDIM + d) * HDIM + c];
        g_hpart[a * HDIM + c] = hp;
    }
}

// ---------------------------------------------------------------------------
extern "C" void kernel_launch(void* const* d_in, const int* in_sizes, int n_in,
                              void* d_out, int out_size)
{
    const float* hidden = (const float*)d_in[0];
    const float* gt     = (const float*)d_in[1];
    const float* W_emb  = (const float*)d_in[2];
    const float* b_emb  = (const float*)d_in[3];
    const float* W_ih   = (const float*)d_in[4];
    const float* W_hh   = (const float*)d_in[5];
    const float* b_ih   = (const float*)d_in[6];
    const float* b_hh   = (const float*)d_in[7];
    const float* W_pos  = (const float*)d_in[8];
    const float* b_pos  = (const float*)d_in[9];
    const float* W_rel  = (const float*)d_in[10];
    const float* b_rel  = (const float*)d_in[11];
    const float* W_pool = (const float*)d_in[12];
    const float* b_pool = (const float*)d_in[13];
    float* out = (float*)d_out;

    init_kernel<<<BATCH + G3, 64>>>(hidden, gt, W_ih, W_hh, W_rel, W_pool, b_pool, out);
    for (int s = 0; s < PRE; ++s) {
        spool_kernel<<<2 * BATCH, 256>>>(W_pool, b_rel);
        update_kernel<<<BATCH / 8, 256>>>(W_emb, b_emb, b_ih, b_hh,
                                          W_pos, b_pos, W_rel, W_pool, b_pool,
                                          out, s);
    }
}

// round 3
// speedup vs baseline: 1.5070x; 1.5070x over previous
#include <cuda_runtime.h>
#include <math.h>
#include <stdint.h>

// Problem constants
#define BATCH 512
#define HDIM  64
#define EDIM  64
#define HPDIM 64
#define OBS   8
#define PRE   12
#define G3    192   // 3*H

// Scratch (device globals — no allocation allowed)
__device__ float g_h[BATCH * HDIM];          // GRU hidden state
__device__ float g_u4[(BATCH/8) * HDIM * 8]; // u in [j/8][k][j%8] layout
__device__ float g_hp4[(BATCH/8) * HDIM * 8];// hpart in [j/8][c][j%8] layout
__device__ float g_pooled[4 * BATCH * HDIM]; // four j-quarters, maxed in update
__device__ float g_WihT[HDIM * G3];          // W_ih transposed [d][g]
__device__ float g_WhhT[HDIM * G3];          // W_hh transposed [d][g]
__device__ uint4 g_Bfrag[64 * 32];           // per (ct,kt,lane): {whi0, whi1, wlo0, wlo1}

__device__ __forceinline__ uint32_t f2tf32(float x) {
    uint32_t u;
    asm("cvt.rna.tf32.f32 %0, %1;" : "=r"(u) : "f"(x));
    return u;
}

__device__ __forceinline__ void mma_tf32(float& d0, float& d1, float& d2, float& d3,
                                         uint32_t a0, uint32_t a1, uint32_t a2, uint32_t a3,
                                         uint32_t b0, uint32_t b1) {
    asm volatile("mma.sync.aligned.m16n8k8.row.col.f32.tf32.tf32.f32 "
                 "{%0,%1,%2,%3}, {%4,%5,%6,%7}, {%8,%9}, {%0,%1,%2,%3};"
                 : "+f"(d0), "+f"(d1), "+f"(d2), "+f"(d3)
                 : "r"(a0), "r"(a1), "r"(a2), "r"(a3), "r"(b0), "r"(b1));
}

// ---------------------------------------------------------------------------
// Init: copy group_track into out, build u4 from last obs pos, hp4 from
// hidden_state, zero GRU h, transpose W_ih / W_hh, precompute B fragments.
// Grid: BATCH + G3 + 64 blocks x 64 threads.
// ---------------------------------------------------------------------------
__global__ void init_kernel(const float* __restrict__ hidden,
                            const float* __restrict__ gt,
                            const float* __restrict__ W_ih,
                            const float* __restrict__ W_hh,
                            const float* __restrict__ W_rel,
                            const float* __restrict__ W_pool,
                            const float* __restrict__ b_pool,
                            float* __restrict__ out)
{
    int bid = blockIdx.x;
    int c = threadIdx.x;
    if (bid < BATCH) {
        int i = bid;
        // copy observed track: out[i, 0:8, :]
        if (c < 2 * OBS) out[i * 2 * (OBS + PRE) + c] = gt[i * 2 * OBS + c];
        // u4[(i/8)][k=c][i%8] from last observed position
        float px = gt[i * 2 * OBS + 2 * (OBS - 1) + 0];
        float py = gt[i * 2 * OBS + 2 * (OBS - 1) + 1];
        g_u4[(i >> 3) * 512 + c * 8 + (i & 7)] = px * W_rel[c] + py * W_rel[HPDIM + c];
        // hp4[(i/8)][c][i%8] = sum_d hidden[i][d] * W_pool[64+d][c] + b_pool[c]
        float acc = b_pool[c];
        #pragma unroll 8
        for (int d = 0; d < HDIM; ++d)
            acc += hidden[i * HDIM + d] * W_pool[(HPDIM + d) * HDIM + c];
        g_hp4[(i >> 3) * 512 + c * 8 + (i & 7)] = acc;
        g_h[i * HDIM + c] = 0.0f;
    } else if (bid < BATCH + G3) {
        int g = bid - BATCH;   // 0..191
        int d = c;             // 0..63
        g_WihT[d * G3 + g] = W_ih[g * HDIM + d];
        g_WhhT[d * G3 + g] = W_hh[g * HDIM + d];
    } else if (c < 32) {
        // B fragment precompute for one (ct, kt): lane holds whi/wlo at
        // b0 = W[k = kt*8+tig][cc = ct*8+gid], b1 = W[k+4][cc]
        int ctkt = bid - (BATCH + G3);   // 0..63
        int kt = ctkt & 7, ct = ctkt >> 3;
        int tig = c & 3, gid = c >> 2;
        int k0 = kt * 8 + tig;
        int cc = ct * 8 + gid;
        float w0 = W_pool[k0 * HDIM + cc];
        float w1 = W_pool[(k0 + 4) * HDIM + cc];
        uint32_t h0 = f2tf32(w0);
        uint32_t h1 = f2tf32(w1);
        uint32_t l0 = f2tf32(w0 - __uint_as_float(h0));
        uint32_t l1 = f2tf32(w1 - __uint_as_float(h1));
        g_Bfrag[ctkt * 32 + c] = make_uint4(h0, h1, l0, l1);
    }
}

// ---------------------------------------------------------------------------
// Spool (tensor cores): for agent i and one j-quarter (128 j), compute
//   pooled[i][c] = max_j relu( relu(u_j - u_i + b_rel) @ Wp1 + hpart_j )[c]
// using tf32 mma.sync m16n8k8 with w split hi+lo for precision.
// Grid: 2048 blocks (i = bid>>2, quarter = bid&3) x 128 threads (4 warps).
// Each warp handles a 32-j pair (two 16-row jtiles sharing B fragments).
// ---------------------------------------------------------------------------
__global__ void __launch_bounds__(128, 3) spool_kernel(const float* __restrict__ b_rel)
{
    __shared__ float ar[HDIM];       // b_rel[k] - u_i[k]
    __shared__ float red[4][HDIM];   // cross-warp max reduction

    int i = blockIdx.x >> 2;
    int q = blockIdx.x & 3;
    int t = threadIdx.x;
    int w = t >> 5, l = t & 31;
    int gid = l >> 2, tig = l & 3;

    if (t < HDIM)
        ar[t] = b_rel[t] - g_u4[(i >> 3) * 512 + t * 8 + (i & 7)];
    __syncthreads();

    int jb = q * 128 + w * 32;

    // Build A fragments (tf32 e values) for both jtiles, all 8 ktiles.
    // a[jt][kt][0] = e(j=jbase+gid,   k=kt*8+tig)
    // a[jt][kt][1] = e(j=jbase+gid+8, k)        (row +8)
    // a[jt][kt][2] = e(j=jbase+gid,   k+4)
    // a[jt][kt][3] = e(j=jbase+gid+8, k+4)
    uint32_t afr[2][8][4];
    #pragma unroll
    for (int jt = 0; jt < 2; ++jt) {
        int jbase = jb + jt * 16;
        const float* u0 = &g_u4[(jbase >> 3) * 512];        // rows j..j+7
        const float* u1 = u0 + 512;                          // rows j+8..j+15
        #pragma unroll
        for (int kt = 0; kt < 8; ++kt) {
            int k0 = kt * 8 + tig;
            float a0v = ar[k0], a1v = ar[k0 + 4];
            float e00 = fmaxf(u0[k0 * 8 + gid]       + a0v, 0.0f);
            float e10 = fmaxf(u1[k0 * 8 + gid]       + a0v, 0.0f);
            float e01 = fmaxf(u0[(k0 + 4) * 8 + gid] + a1v, 0.0f);
            float e11 = fmaxf(u1[(k0 + 4) * 8 + gid] + a1v, 0.0f);
            afr[jt][kt][0] = f2tf32(e00);
            afr[jt][kt][1] = f2tf32(e10);
            afr[jt][kt][2] = f2tf32(e01);
            afr[jt][kt][3] = f2tf32(e11);
        }
    }

    // mx[jt][ct][p]: per-lane max over the rows this lane owns
    float mx[2][8][2];

    #pragma unroll
    for (int ct = 0; ct < 8; ++ct) {
        int cb = ct * 8;
        // C init = hpart fragments. D layout: c0=(gid, cb+2tig), c1=(gid, +1),
        // c2=(gid+8, cb+2tig), c3=(gid+8, +1)
        float d[2][4];
        #pragma unroll
        for (int jt = 0; jt < 2; ++jt) {
            int jbase = jb + jt * 16;
            const float* hp0 = &g_hp4[(jbase >> 3) * 512];
            const float* hp1 = hp0 + 512;
            int co = (cb + 2 * tig) * 8 + gid;
            d[jt][0] = hp0[co];
            d[jt][1] = hp0[co + 8];
            d[jt][2] = hp1[co];
            d[jt][3] = hp1[co + 8];
        }
        #pragma unroll
        for (int kt = 0; kt < 8; ++kt) {
            uint4 B = g_Bfrag[(ct * 8 + kt) * 32 + l];
            mma_tf32(d[0][0], d[0][1], d[0][2], d[0][3],
                     afr[0][kt][0], afr[0][kt][1], afr[0][kt][2], afr[0][kt][3],
                     B.x, B.y);
            mma_tf32(d[0][0], d[0][1], d[0][2], d[0][3],
                     afr[0][kt][0], afr[0][kt][1], afr[0][kt][2], afr[0][kt][3],
                     B.z, B.w);
            mma_tf32(d[1][0], d[1][1], d[1][2], d[1][3],
                     afr[1][kt][0], afr[1][kt][1], afr[1][kt][2], afr[1][kt][3],
                     B.x, B.y);
            mma_tf32(d[1][0], d[1][1], d[1][2], d[1][3],
                     afr[1][kt][0], afr[1][kt][1], afr[1][kt][2], afr[1][kt][3],
                     B.z, B.w);
        }
        #pragma unroll
        for (int jt = 0; jt < 2; ++jt) {
            // relu implicit: max starts at 0
            mx[jt][ct][0] = fmaxf(fmaxf(d[jt][0], d[jt][2]), 0.0f);
            mx[jt][ct][1] = fmaxf(fmaxf(d[jt][1], d[jt][3]), 0.0f);
        }
    }

    // Reduce across jtiles + across lane groups (gid), write per-warp result
    #pragma unroll
    for (int ct = 0; ct < 8; ++ct) {
        #pragma unroll
        for (int p = 0; p < 2; ++p) {
            float v = fmaxf(mx[0][ct][p], mx[1][ct][p]);
            v = fmaxf(v, __shfl_xor_sync(0xffffffffu, v, 4));
            v = fmaxf(v, __shfl_xor_sync(0xffffffffu, v, 8));
            v = fmaxf(v, __shfl_xor_sync(0xffffffffu, v, 16));
            if (gid == 0) red[w][ct * 8 + 2 * tig + p] = v;
        }
    }
    __syncthreads();
    if (t < HDIM) {
        float m = fmaxf(fmaxf(red[0][t], red[1][t]), fmaxf(red[2][t], red[3][t]));
        g_pooled[(q * BATCH + i) * HDIM + t] = m;
    }
}

// ---------------------------------------------------------------------------
// Update: pooled -> pos -> emb -> GRU(h) ; write pos to out; produce next
// step's u4 (from pos) and hp4 (from new h).
// Grid: 64 blocks x 256 threads; warp w handles agent a = bid*8 + w.
// ---------------------------------------------------------------------------
__global__ void __launch_bounds__(256) update_kernel(
    const float* __restrict__ W_emb, const float* __restrict__ b_emb,
    const float* __restrict__ b_ih,  const float* __restrict__ b_hh,
    const float* __restrict__ W_pos, const float* __restrict__ b_pos,
    const float* __restrict__ W_rel, const float* __restrict__ W_pool,
    const float* __restrict__ b_pool, float* __restrict__ out, int step)
{
    __shared__ float emb_s[8][HDIM];
    __shared__ float h_s[8][HDIM];
    __shared__ float hn_s[8][HDIM];

    int w = threadIdx.x >> 5, l = threadIdx.x & 31;
    int a = blockIdx.x * 8 + w;

    // pooled = max over the four spool quarters
    float p0 = g_pooled[a * HDIM + l];
    float p1 = g_pooled[a * HDIM + l + 32];
    #pragma unroll
    for (int qq = 1; qq < 4; ++qq) {
        p0 = fmaxf(p0, g_pooled[(qq * BATCH + a) * HDIM + l]);
        p1 = fmaxf(p1, g_pooled[(qq * BATCH + a) * HDIM + l + 32]);
    }

    // pos = pooled @ W_pos + b_pos  (warp butterfly reduction)
    float px = p0 * W_pos[l * 2 + 0] + p1 * W_pos[(l + 32) * 2 + 0];
    float py = p0 * W_pos[l * 2 + 1] + p1 * W_pos[(l + 32) * 2 + 1];
    #pragma unroll
    for (int s = 16; s; s >>= 1) {
        px += __shfl_xor_sync(0xffffffffu, px, s);
        py += __shfl_xor_sync(0xffffffffu, py, s);
    }
    px += b_pos[0]; py += b_pos[1];

    if (l == 0) {
        out[a * 2 * (OBS + PRE) + (OBS + step) * 2 + 0] = px;
        out[a * 2 * (OBS + PRE) + (OBS + step) * 2 + 1] = py;
    }

    // next-step u4
    int ub = (a >> 3) * 512 + (a & 7);
    g_u4[ub + l * 8]        = px * W_rel[l]      + py * W_rel[HPDIM + l];
    g_u4[ub + (l + 32) * 8] = px * W_rel[l + 32] + py * W_rel[HPDIM + l + 32];

    // emb = pos @ W_emb + b_emb ; stage h
    emb_s[w][l]      = px * W_emb[l]      + py * W_emb[EDIM + l]      + b_emb[l];
    emb_s[w][l + 32] = px * W_emb[l + 32] + py * W_emb[EDIM + l + 32] + b_emb[l + 32];
    float h0 = g_h[a * HDIM + l];
    float h1 = g_h[a * HDIM + l + 32];
    h_s[w][l] = h0; h_s[w][l + 32] = h1;
    __syncwarp();

    // GRU gates for columns c = l, l+32
    float hn[2];
    #pragma unroll
    for (int cc = 0; cc < 2; ++cc) {
        int c = l + cc * 32;
        float gir = b_ih[c], giz = b_ih[64 + c], gin = b_ih[128 + c];
        float ghr = b_hh[c], ghz = b_hh[64 + c], ghn = b_hh[128 + c];
        #pragma unroll 8
        for (int d = 0; d < HDIM; ++d) {
            float ed = emb_s[w][d], hd = h_s[w][d];
            gir += ed * g_WihT[d * G3 + c];
            giz += ed * g_WihT[d * G3 + 64 + c];
            gin += ed * g_WihT[d * G3 + 128 + c];
            ghr += hd * g_WhhT[d * G3 + c];
            ghz += hd * g_WhhT[d * G3 + 64 + c];
            ghn += hd * g_WhhT[d * G3 + 128 + c];
        }
        float r = 1.0f / (1.0f + expf(-(gir + ghr)));
        float z = 1.0f / (1.0f + expf(-(giz + ghz)));
        float n = tanhf(gin + r * ghn);
        float ho = cc ? h1 : h0;
        hn[cc] = (1.0f - z) * n + z * ho;
    }
    g_h[a * HDIM + l]      = hn[0];
    g_h[a * HDIM + l + 32] = hn[1];
    hn_s[w][l] = hn[0]; hn_s[w][l + 32] = hn[1];
    __syncwarp();

    // next-step hp4 = h_new @ Wp2 + b_pool
    int hb = (a >> 3) * 512 + (a & 7);
    #pragma unroll
    for (int cc = 0; cc < 2; ++cc) {
        int c = l + cc * 32;
        float hp = b_pool[c];
        #pragma unroll 8
        for (int d = 0; d < HDIM; ++d)
            hp += hn_s[w][d] * W_pool[(HPDIM + d) * HDIM + c];
        g_hp4[hb + c * 8] = hp;
    }
}

// ---------------------------------------------------------------------------
extern "C" void kernel_launch(void* const* d_in, const int* in_sizes, int n_in,
                              void* d_out, int out_size)
{
    const float* hidden = (const float*)d_in[0];
    const float* gt     = (const float*)d_in[1];
    const float* W_emb  = (const float*)d_in[2];
    const float* b_emb  = (const float*)d_in[3];
    const float* W_ih   = (const float*)d_in[4];
    const float* W_hh   = (const float*)d_in[5];
    const float* b_ih   = (const float*)d_in[6];
    const float* b_hh   = (const float*)d_in[7];
    const float* W_pos  = (const float*)d_in[8];
    const float* b_pos  = (const float*)d_in[9];
    const float* W_rel  = (const float*)d_in[10];
    const float* b_rel  = (const float*)d_in[11];
    const float* W_pool = (const float*)d_in[12];
    const float* b_pool = (const float*)d_in[13];
    float* out = (float*)d_out;

    init_kernel<<<BATCH + G3 + 64, 64>>>(hidden, gt, W_ih, W_hh, W_rel, W_pool, b_pool, out);
    for (int s = 0; s < PRE; ++s) {
        spool_kernel<<<4 * BATCH, 128>>>(b_rel);
        update_kernel<<<BATCH / 8, 256>>>(W_emb, b_emb, b_ih, b_hh,
                                          W_pos, b_pos, W_rel, W_pool, b_pool,
                                          out, s);
    }
}

// round 4
// speedup vs baseline: 2.4529x; 1.6277x over previous
#include <cuda_runtime.h>
#include <math.h>
#include <stdint.h>

// Problem constants
#define BATCH 512
#define HDIM  64
#define EDIM  64
#define HPDIM 64
#define OBS   8
#define PRE   12
#define G3    192   // 3*H

// Scratch (device globals — no allocation allowed)
__device__ float g_h[BATCH * HDIM];          // GRU hidden state
__device__ float g_u4[(BATCH/8) * HDIM * 8]; // u in [j/8][k][j%8] layout
__device__ float g_hp4[(BATCH/8) * HDIM * 8];// hpart in [j/8][c][j%8] layout
__device__ float g_pooled[4 * BATCH * HDIM]; // four j-quarters, maxed in update
__device__ float g_WihT[HDIM * G3];          // W_ih transposed [d][g]
__device__ float g_WhhT[HDIM * G3];          // W_hh transposed [d][g]
__device__ uint2 g_Bfrag[64 * 32];           // per (ct,kt,lane): {w0, w1} tf32

__device__ __forceinline__ uint32_t f2tf32(float x) {
    uint32_t u;
    asm("cvt.rna.tf32.f32 %0, %1;" : "=r"(u) : "f"(x));
    return u;
}

__device__ __forceinline__ void mma_tf32(float& d0, float& d1, float& d2, float& d3,
                                         uint32_t a0, uint32_t a1, uint32_t a2, uint32_t a3,
                                         uint32_t b0, uint32_t b1) {
    asm volatile("mma.sync.aligned.m16n8k8.row.col.f32.tf32.tf32.f32 "
                 "{%0,%1,%2,%3}, {%4,%5,%6,%7}, {%8,%9}, {%0,%1,%2,%3};"
                 : "+f"(d0), "+f"(d1), "+f"(d2), "+f"(d3)
                 : "r"(a0), "r"(a1), "r"(a2), "r"(a3), "r"(b0), "r"(b1));
}

__device__ __forceinline__ float fsigmoid(float x) {
    return 1.0f / (1.0f + __expf(-x));
}
__device__ __forceinline__ float ftanh(float x) {
    return 2.0f / (1.0f + __expf(-2.0f * x)) - 1.0f;
}

// ---------------------------------------------------------------------------
// Init: copy group_track into out, build u4 from last obs pos, hp4 from
// hidden_state, zero GRU h, transpose W_ih / W_hh, precompute B fragments.
// Grid: BATCH + G3 + 64 blocks x 64 threads.
// ---------------------------------------------------------------------------
__global__ void init_kernel(const float* __restrict__ hidden,
                            const float* __restrict__ gt,
                            const float* __restrict__ W_ih,
                            const float* __restrict__ W_hh,
                            const float* __restrict__ W_rel,
                            const float* __restrict__ W_pool,
                            const float* __restrict__ b_pool,
                            float* __restrict__ out)
{
    int bid = blockIdx.x;
    int c = threadIdx.x;
    if (bid < BATCH) {
        int i = bid;
        // copy observed track: out[i, 0:8, :]
        if (c < 2 * OBS) out[i * 2 * (OBS + PRE) + c] = gt[i * 2 * OBS + c];
        // u4[(i/8)][k=c][i%8] from last observed position
        float px = gt[i * 2 * OBS + 2 * (OBS - 1) + 0];
        float py = gt[i * 2 * OBS + 2 * (OBS - 1) + 1];
        g_u4[(i >> 3) * 512 + c * 8 + (i & 7)] = px * W_rel[c] + py * W_rel[HPDIM + c];
        // hp4[(i/8)][c][i%8] = sum_d hidden[i][d] * W_pool[64+d][c] + b_pool[c]
        float acc = b_pool[c];
        #pragma unroll 8
        for (int d = 0; d < HDIM; ++d)
            acc += hidden[i * HDIM + d] * W_pool[(HPDIM + d) * HDIM + c];
        g_hp4[(i >> 3) * 512 + c * 8 + (i & 7)] = acc;
        g_h[i * HDIM + c] = 0.0f;
    } else if (bid < BATCH + G3) {
        int g = bid - BATCH;   // 0..191
        int d = c;             // 0..63
        g_WihT[d * G3 + g] = W_ih[g * HDIM + d];
        g_WhhT[d * G3 + g] = W_hh[g * HDIM + d];
    } else if (c < 32) {
        // B fragment precompute for one (ct, kt): lane holds tf32 w at
        // b0 = W[k = kt*8+tig][cc = ct*8+gid], b1 = W[k+4][cc]
        int ctkt = bid - (BATCH + G3);   // 0..63
        int kt = ctkt & 7, ct = ctkt >> 3;
        int tig = c & 3, gid = c >> 2;
        int k0 = kt * 8 + tig;
        int cc = ct * 8 + gid;
        uint32_t h0 = f2tf32(W_pool[k0 * HDIM + cc]);
        uint32_t h1 = f2tf32(W_pool[(k0 + 4) * HDIM + cc]);
        g_Bfrag[ctkt * 32 + c] = make_uint2(h0, h1);
    }
}

// ---------------------------------------------------------------------------
// Spool (tensor cores): for agent i and one j-quarter (128 j), compute
//   pooled[i][c] = max_j relu( relu(u_j - u_i + b_rel) @ Wp1 + hpart_j )[c]
// using tf32 mma.sync m16n8k8.
// Grid: 2048 blocks (i = bid>>2, quarter = bid&3) x 128 threads (4 warps).
// Each warp handles a 32-j pair (two 16-row jtiles sharing B fragments).
// ---------------------------------------------------------------------------
__global__ void __launch_bounds__(128) spool_kernel(const float* __restrict__ b_rel)
{
    __shared__ float ar[HDIM];       // b_rel[k] - u_i[k]
    __shared__ float red[4][HDIM];   // cross-warp max reduction

    int i = blockIdx.x >> 2;
    int q = blockIdx.x & 3;
    int t = threadIdx.x;
    int w = t >> 5, l = t & 31;
    int gid = l >> 2, tig = l & 3;

    if (t < HDIM)
        ar[t] = b_rel[t] - g_u4[(i >> 3) * 512 + t * 8 + (i & 7)];
    __syncthreads();

    int jb = q * 128 + w * 32;

    // Build A fragments (tf32 e values) for both jtiles, all 8 ktiles.
    uint32_t afr[2][8][4];
    #pragma unroll
    for (int jt = 0; jt < 2; ++jt) {
        int jbase = jb + jt * 16;
        const float* u0 = &g_u4[(jbase >> 3) * 512];        // rows j..j+7
        const float* u1 = u0 + 512;                          // rows j+8..j+15
        #pragma unroll
        for (int kt = 0; kt < 8; ++kt) {
            int k0 = kt * 8 + tig;
            float a0v = ar[k0], a1v = ar[k0 + 4];
            float e00 = fmaxf(u0[k0 * 8 + gid]       + a0v, 0.0f);
            float e10 = fmaxf(u1[k0 * 8 + gid]       + a0v, 0.0f);
            float e01 = fmaxf(u0[(k0 + 4) * 8 + gid] + a1v, 0.0f);
            float e11 = fmaxf(u1[(k0 + 4) * 8 + gid] + a1v, 0.0f);
            afr[jt][kt][0] = f2tf32(e00);
            afr[jt][kt][1] = f2tf32(e10);
            afr[jt][kt][2] = f2tf32(e01);
            afr[jt][kt][3] = f2tf32(e11);
        }
    }

    // mx[jt][ct][p]: per-lane max over the rows this lane owns
    float mx[2][8][2];

    #pragma unroll
    for (int ct = 0; ct < 8; ++ct) {
        int cb = ct * 8;
        // C init = hpart fragments. D layout: c0=(gid, cb+2tig), c1=(gid, +1),
        // c2=(gid+8, cb+2tig), c3=(gid+8, +1)
        float d[2][4];
        #pragma unroll
        for (int jt = 0; jt < 2; ++jt) {
            int jbase = jb + jt * 16;
            const float* hp0 = &g_hp4[(jbase >> 3) * 512];
            const float* hp1 = hp0 + 512;
            int co = (cb + 2 * tig) * 8 + gid;
            d[jt][0] = hp0[co];
            d[jt][1] = hp0[co + 8];
            d[jt][2] = hp1[co];
            d[jt][3] = hp1[co + 8];
        }
        #pragma unroll
        for (int kt = 0; kt < 8; ++kt) {
            uint2 B = g_Bfrag[(ct * 8 + kt) * 32 + l];
            mma_tf32(d[0][0], d[0][1], d[0][2], d[0][3],
                     afr[0][kt][0], afr[0][kt][1], afr[0][kt][2], afr[0][kt][3],
                     B.x, B.y);
            mma_tf32(d[1][0], d[1][1], d[1][2], d[1][3],
                     afr[1][kt][0], afr[1][kt][1], afr[1][kt][2], afr[1][kt][3],
                     B.x, B.y);
        }
        #pragma unroll
        for (int jt = 0; jt < 2; ++jt) {
            // relu implicit: max starts at 0
            mx[jt][ct][0] = fmaxf(fmaxf(d[jt][0], d[jt][2]), 0.0f);
            mx[jt][ct][1] = fmaxf(fmaxf(d[jt][1], d[jt][3]), 0.0f);
        }
    }

    // Reduce across jtiles + across lane groups (gid), write per-warp result
    #pragma unroll
    for (int ct = 0; ct < 8; ++ct) {
        #pragma unroll
        for (int p = 0; p < 2; ++p) {
            float v = fmaxf(mx[0][ct][p], mx[1][ct][p]);
            v = fmaxf(v, __shfl_xor_sync(0xffffffffu, v, 4));
            v = fmaxf(v, __shfl_xor_sync(0xffffffffu, v, 8));
            v = fmaxf(v, __shfl_xor_sync(0xffffffffu, v, 16));
            if (gid == 0) red[w][ct * 8 + 2 * tig + p] = v;
        }
    }
    __syncthreads();
    if (t < HDIM) {
        float m = fmaxf(fmaxf(red[0][t], red[1][t]), fmaxf(red[2][t], red[3][t]));
        g_pooled[(q * BATCH + i) * HDIM + t] = m;
    }
}

// ---------------------------------------------------------------------------
// Update: pooled -> pos -> emb -> GRU(h) ; write pos to out; produce next
// step's u4 (from pos) and hp4 (from new h).
// Grid: 128 blocks x 128 threads (4 warps); warp w handles agent bid*4 + w.
// ---------------------------------------------------------------------------
__global__ void __launch_bounds__(128) update_kernel(
    const float* __restrict__ W_emb, const float* __restrict__ b_emb,
    const float* __restrict__ b_ih,  const float* __restrict__ b_hh,
    const float* __restrict__ W_pos, const float* __restrict__ b_pos,
    const float* __restrict__ W_rel, const float* __restrict__ W_pool,
    const float* __restrict__ b_pool, float* __restrict__ out, int step)
{
    __shared__ float emb_s[4][HDIM];
    __shared__ float h_s[4][HDIM];
    __shared__ float hn_s[4][HDIM];

    int w = threadIdx.x >> 5, l = threadIdx.x & 31;
    int a = blockIdx.x * 4 + w;

    // pooled = max over the four spool quarters
    float p0 = g_pooled[a * HDIM + l];
    float p1 = g_pooled[a * HDIM + l + 32];
    #pragma unroll
    for (int qq = 1; qq < 4; ++qq) {
        p0 = fmaxf(p0, g_pooled[(qq * BATCH + a) * HDIM + l]);
        p1 = fmaxf(p1, g_pooled[(qq * BATCH + a) * HDIM + l + 32]);
    }

    // pos = pooled @ W_pos + b_pos  (warp butterfly reduction)
    float px = p0 * W_pos[l * 2 + 0] + p1 * W_pos[(l + 32) * 2 + 0];
    float py = p0 * W_pos[l * 2 + 1] + p1 * W_pos[(l + 32) * 2 + 1];
    #pragma unroll
    for (int s = 16; s; s >>= 1) {
        px += __shfl_xor_sync(0xffffffffu, px, s);
        py += __shfl_xor_sync(0xffffffffu, py, s);
    }
    px += b_pos[0]; py += b_pos[1];

    if (l == 0) {
        out[a * 2 * (OBS + PRE) + (OBS + step) * 2 + 0] = px;
        out[a * 2 * (OBS + PRE) + (OBS + step) * 2 + 1] = py;
    }

    // next-step u4
    int ub = (a >> 3) * 512 + (a & 7);
    g_u4[ub + l * 8]        = px * W_rel[l]      + py * W_rel[HPDIM + l];
    g_u4[ub + (l + 32) * 8] = px * W_rel[l + 32] + py * W_rel[HPDIM + l + 32];

    // emb = pos @ W_emb + b_emb ; stage h
    emb_s[w][l]      = px * W_emb[l]      + py * W_emb[EDIM + l]      + b_emb[l];
    emb_s[w][l + 32] = px * W_emb[l + 32] + py * W_emb[EDIM + l + 32] + b_emb[l + 32];
    float h0 = g_h[a * HDIM + l];
    float h1 = g_h[a * HDIM + l + 32];
    h_s[w][l] = h0; h_s[w][l + 32] = h1;
    __syncwarp();

    // GRU gates for columns c = l, l+32
    float hn[2];
    #pragma unroll
    for (int cc = 0; cc < 2; ++cc) {
        int c = l + cc * 32;
        float gir = b_ih[c], giz = b_ih[64 + c], gin = b_ih[128 + c];
        float ghr = b_hh[c], ghz = b_hh[64 + c], ghn = b_hh[128 + c];
        #pragma unroll 8
        for (int d = 0; d < HDIM; ++d) {
            float ed = emb_s[w][d], hd = h_s[w][d];
            gir += ed * g_WihT[d * G3 + c];
            giz += ed * g_WihT[d * G3 + 64 + c];
            gin += ed * g_WihT[d * G3 + 128 + c];
            ghr += hd * g_WhhT[d * G3 + c];
            ghz += hd * g_WhhT[d * G3 + 64 + c];
            ghn += hd * g_WhhT[d * G3 + 128 + c];
        }
        float r = fsigmoid(gir + ghr);
        float z = fsigmoid(giz + ghz);
        float n = ftanh(gin + r * ghn);
        float ho = cc ? h1 : h0;
        hn[cc] = (1.0f - z) * n + z * ho;
    }
    g_h[a * HDIM + l]      = hn[0];
    g_h[a * HDIM + l + 32] = hn[1];
    hn_s[w][l] = hn[0]; hn_s[w][l + 32] = hn[1];
    __syncwarp();

    // next-step hp4 = h_new @ Wp2 + b_pool
    int hb = (a >> 3) * 512 + (a & 7);
    #pragma unroll
    for (int cc = 0; cc < 2; ++cc) {
        int c = l + cc * 32;
        float hp = b_pool[c];
        #pragma unroll 8
        for (int d = 0; d < HDIM; ++d)
            hp += hn_s[w][d] * W_pool[(HPDIM + d) * HDIM + c];
        g_hp4[hb + c * 8] = hp;
    }
}

// ---------------------------------------------------------------------------
extern "C" void kernel_launch(void* const* d_in, const int* in_sizes, int n_in,
                              void* d_out, int out_size)
{
    const float* hidden = (const float*)d_in[0];
    const float* gt     = (const float*)d_in[1];
    const float* W_emb  = (const float*)d_in[2];
    const float* b_emb  = (const float*)d_in[3];
    const float* W_ih   = (const float*)d_in[4];
    const float* W_hh   = (const float*)d_in[5];
    const float* b_ih   = (const float*)d_in[6];
    const float* b_hh   = (const float*)d_in[7];
    const float* W_pos  = (const float*)d_in[8];
    const float* b_pos  = (const float*)d_in[9];
    const float* W_rel  = (const float*)d_in[10];
    const float* b_rel  = (const float*)d_in[11];
    const float* W_pool = (const float*)d_in[12];
    const float* b_pool = (const float*)d_in[13];
    float* out = (float*)d_out;

    init_kernel<<<BATCH + G3 + 64, 64>>>(hidden, gt, W_ih, W_hh, W_rel, W_pool, b_pool, out);
    for (int s = 0; s < PRE; ++s) {
        spool_kernel<<<4 * BATCH, 128>>>(b_rel);
        update_kernel<<<BATCH / 4, 128>>>(W_emb, b_emb, b_ih, b_hh,
                                          W_pos, b_pos, W_rel, W_pool, b_pool,
                                          out, s);
    }
}

// round 5
// speedup vs baseline: 3.6314x; 1.4805x over previous
#include <cuda_runtime.h>
#include <math.h>
#include <stdint.h>

// Problem constants
#define BATCH 512
#define HDIM  64
#define OBS   8
#define PRE   12
#define G3    192   // 3*H

// Scratch (device globals — no allocation allowed)
__device__ float  g_h[BATCH * HDIM];                 // GRU hidden state (per-agent, race-free)
// u double-buffered: [buf][(j>>3)*256 + (kt*4+tig)*8 + (j&7)] = {u[j][kt*8+tig], u[j][kt*8+tig+4]}
__device__ float2 g_u2[2][(BATCH / 8) * 32 * 8];
// hpart double-buffered: [buf][(j>>3)*256 + cp*8 + (j&7)] = {hp[j][2cp], hp[j][2cp+1]}
__device__ float2 g_hp2[2][(BATCH / 8) * 32 * 8];
__device__ float  g_WihT[HDIM * G3];                 // W_ih transposed [d][g]
__device__ float  g_WhhT[HDIM * G3];                 // W_hh transposed [d][g]
// B fragments: [(ct*4+ktp)*32 + lane] = {B(2ktp).x, B(2ktp).y, B(2ktp+1).x, B(2ktp+1).y}
__device__ uint4  g_B4[32 * 32];

__device__ __forceinline__ uint32_t f2tf32(float x) {
    uint32_t u;
    asm("cvt.rna.tf32.f32 %0, %1;" : "=r"(u) : "f"(x));
    return u;
}

__device__ __forceinline__ void mma_tf32(float& d0, float& d1, float& d2, float& d3,
                                         uint32_t a0, uint32_t a1, uint32_t a2, uint32_t a3,
                                         uint32_t b0, uint32_t b1) {
    asm volatile("mma.sync.aligned.m16n8k8.row.col.f32.tf32.tf32.f32 "
                 "{%0,%1,%2,%3}, {%4,%5,%6,%7}, {%8,%9}, {%0,%1,%2,%3};"
                 : "+f"(d0), "+f"(d1), "+f"(d2), "+f"(d3)
                 : "r"(a0), "r"(a1), "r"(a2), "r"(a3), "r"(b0), "r"(b1));
}

__device__ __forceinline__ float fsigmoid(float x) {
    return 1.0f / (1.0f + __expf(-x));
}
__device__ __forceinline__ float ftanh(float x) {
    return 2.0f / (1.0f + __expf(-2.0f * x)) - 1.0f;
}

// scalar index into the float2 u/hp layouts, viewed as float
__device__ __forceinline__ int u_scalar_idx(int j, int k) {
    int kt = k >> 3, tig = k & 3, s = (k >> 2) & 1;
    return (j >> 3) * 512 + (kt * 4 + tig) * 16 + (j & 7) * 2 + s;
}
__device__ __forceinline__ int hp_scalar_idx(int j, int c) {
    return (j >> 3) * 512 + (c >> 1) * 16 + (j & 7) * 2 + (c & 1);
}

// ---------------------------------------------------------------------------
// Init: copy group_track into out, build u2/hp2 (buf 0), zero GRU h,
// transpose W_ih / W_hh, precompute B fragments.
// Grid: BATCH + G3 + 32 blocks x 64 threads.
// ---------------------------------------------------------------------------
__global__ void init_kernel(const float* __restrict__ hidden,
                            const float* __restrict__ gt,
                            const float* __restrict__ W_ih,
                            const float* __restrict__ W_hh,
                            const float* __restrict__ W_rel,
                            const float* __restrict__ W_pool,
                            const float* __restrict__ b_pool,
                            float* __restrict__ out)
{
    int bid = blockIdx.x;
    int c = threadIdx.x;
    if (bid < BATCH) {
        int i = bid;
        // copy observed track: out[i, 0:8, :]
        if (c < 2 * OBS) out[i * 2 * (OBS + PRE) + c] = gt[i * 2 * OBS + c];
        // u (buf 0) from last observed position
        float px = gt[i * 2 * OBS + 2 * (OBS - 1) + 0];
        float py = gt[i * 2 * OBS + 2 * (OBS - 1) + 1];
        ((float*)g_u2[0])[u_scalar_idx(i, c)] = px * W_rel[c] + py * W_rel[HDIM + c];
        // hp (buf 0) from hidden_state
        float acc = b_pool[c];
        #pragma unroll 8
        for (int d = 0; d < HDIM; ++d)
            acc += hidden[i * HDIM + d] * W_pool[(HDIM + d) * HDIM + c];
        ((float*)g_hp2[0])[hp_scalar_idx(i, c)] = acc;
        g_h[i * HDIM + c] = 0.0f;
    } else if (bid < BATCH + G3) {
        int g = bid - BATCH;   // 0..191
        int d = c;             // 0..63
        g_WihT[d * G3 + g] = W_ih[g * HDIM + d];
        g_WhhT[d * G3 + g] = W_hh[g * HDIM + d];
    } else if (c < 32) {
        // B fragment precompute for one (ct, ktp): covers kt = 2ktp, 2ktp+1
        int q = bid - (BATCH + G3);   // 0..31
        int ktp = q & 3, ct = q >> 2;
        int tig = c & 3, gid = c >> 2;
        int cc = ct * 8 + gid;
        int ka = (2 * ktp) * 8 + tig;
        int kb = (2 * ktp + 1) * 8 + tig;
        uint32_t b0 = f2tf32(W_pool[ka * HDIM + cc]);
        uint32_t b1 = f2tf32(W_pool[(ka + 4) * HDIM + cc]);
        uint32_t b2 = f2tf32(W_pool[kb * HDIM + cc]);
        uint32_t b3 = f2tf32(W_pool[(kb + 4) * HDIM + cc]);
        g_B4[q * 32 + c] = make_uint4(b0, b1, b2, b3);
    }
}

// ---------------------------------------------------------------------------
// Fused step: block = one agent i. Spool over all 512 j (4 warps x 4 pairs of
// 32 j), then pos -> out, emb, GRU, and next-step u/hp (double-buffered).
// Grid: 512 blocks x 128 threads.
// ---------------------------------------------------------------------------
__global__ void __launch_bounds__(128, 4) step_kernel(
    const float* __restrict__ b_rel,
    const float* __restrict__ W_emb, const float* __restrict__ b_emb,
    const float* __restrict__ b_ih,  const float* __restrict__ b_hh,
    const float* __restrict__ W_pos, const float* __restrict__ b_pos,
    const float* __restrict__ W_rel, const float* __restrict__ W_pool,
    const float* __restrict__ b_pool, float* __restrict__ out, int step)
{
    __shared__ float ar_s[HDIM];      // b_rel[k] - u_i[k]
    __shared__ float red_s[4][HDIM];  // cross-warp max reduction
    __shared__ float pooled_s[HDIM];
    __shared__ float pos_s[2];
    __shared__ float emb_s[HDIM];
    __shared__ float hv_s[HDIM];
    __shared__ float hn_s[HDIM];

    int buf  = step & 1;
    int nbuf = buf ^ 1;
    const float2* __restrict__ u2r  = g_u2[buf];
    const float2* __restrict__ hp2r = g_hp2[buf];

    int i = blockIdx.x;
    int t = threadIdx.x;
    int w = t >> 5, l = t & 31;
    int gid = l >> 2, tig = l & 3;

    if (t < HDIM)
        ar_s[t] = b_rel[t] - ((const float*)u2r)[u_scalar_idx(i, t)];
    __syncthreads();

    // per-lane (k, k+4) bias pairs
    float2 ar2[8];
    #pragma unroll
    for (int kt = 0; kt < 8; ++kt) {
        int k0 = kt * 8 + tig;
        ar2[kt] = make_float2(ar_s[k0], ar_s[k0 + 4]);
    }

    float mx[8][2];
    #pragma unroll
    for (int ct = 0; ct < 8; ++ct) { mx[ct][0] = 0.0f; mx[ct][1] = 0.0f; }  // relu => max>=0

    for (int p = 0; p < 4; ++p) {
        int jb = p * 128 + w * 32;
        int rb = (jb >> 3) * 256;   // float2 row-block base (8 rows per 256)

        // A fragments: e = relu(u_j + ar), tf32, for 2 jtiles x 8 ktiles
        uint32_t afr[2][8][4];
        #pragma unroll
        for (int jt = 0; jt < 2; ++jt) {
            int r0 = rb + jt * 512;     // rows jb+16jt .. +7
            #pragma unroll
            for (int kt = 0; kt < 8; ++kt) {
                float2 v0 = u2r[r0 + (kt * 4 + tig) * 8 + gid];
                float2 v1 = u2r[r0 + 256 + (kt * 4 + tig) * 8 + gid];
                afr[jt][kt][0] = f2tf32(fmaxf(v0.x + ar2[kt].x, 0.0f));
                afr[jt][kt][1] = f2tf32(fmaxf(v1.x + ar2[kt].x, 0.0f));
                afr[jt][kt][2] = f2tf32(fmaxf(v0.y + ar2[kt].y, 0.0f));
                afr[jt][kt][3] = f2tf32(fmaxf(v1.y + ar2[kt].y, 0.0f));
            }
        }

        #pragma unroll
        for (int ct = 0; ct < 8; ++ct) {
            // C init = hpart fragments (float2 covers both c columns of a lane)
            float d[2][4];
            #pragma unroll
            for (int jt = 0; jt < 2; ++jt) {
                int r0 = rb + jt * 512;
                float2 c0 = hp2r[r0 + (ct * 4 + tig) * 8 + gid];
                float2 c1 = hp2r[r0 + 256 + (ct * 4 + tig) * 8 + gid];
                d[jt][0] = c0.x; d[jt][1] = c0.y;
                d[jt][2] = c1.x; d[jt][3] = c1.y;
            }
            #pragma unroll
            for (int ktp = 0; ktp < 4; ++ktp) {
                uint4 B = g_B4[(ct * 4 + ktp) * 32 + l];
                mma_tf32(d[0][0], d[0][1], d[0][2], d[0][3],
                         afr[0][2 * ktp][0], afr[0][2 * ktp][1], afr[0][2 * ktp][2], afr[0][2 * ktp][3],
                         B.x, B.y);
                mma_tf32(d[0][0], d[0][1], d[0][2], d[0][3],
                         afr[0][2 * ktp + 1][0], afr[0][2 * ktp + 1][1], afr[0][2 * ktp + 1][2], afr[0][2 * ktp + 1][3],
                         B.z, B.w);
                mma_tf32(d[1][0], d[1][1], d[1][2], d[1][3],
                         afr[1][2 * ktp][0], afr[1][2 * ktp][1], afr[1][2 * ktp][2], afr[1][2 * ktp][3],
                         B.x, B.y);
                mma_tf32(d[1][0], d[1][1], d[1][2], d[1][3],
                         afr[1][2 * ktp + 1][0], afr[1][2 * ktp + 1][1], afr[1][2 * ktp + 1][2], afr[1][2 * ktp + 1][3],
                         B.z, B.w);
            }
            mx[ct][0] = fmaxf(mx[ct][0], fmaxf(fmaxf(d[0][0], d[0][2]), fmaxf(d[1][0], d[1][2])));
            mx[ct][1] = fmaxf(mx[ct][1], fmaxf(fmaxf(d[0][1], d[0][3]), fmaxf(d[1][1], d[1][3])));
        }
    }

    // Reduce across lane groups (gid), write per-warp result
    #pragma unroll
    for (int ct = 0; ct < 8; ++ct) {
        #pragma unroll
        for (int pp = 0; pp < 2; ++pp) {
            float v = mx[ct][pp];
            v = fmaxf(v, __shfl_xor_sync(0xffffffffu, v, 4));
            v = fmaxf(v, __shfl_xor_sync(0xffffffffu, v, 8));
            v = fmaxf(v, __shfl_xor_sync(0xffffffffu, v, 16));
            if (gid == 0) red_s[w][ct * 8 + 2 * tig + pp] = v;
        }
    }
    __syncthreads();
    if (t < HDIM)
        pooled_s[t] = fmaxf(fmaxf(red_s[0][t], red_s[1][t]), fmaxf(red_s[2][t], red_s[3][t]));
    __syncthreads();

    // ---- update tail ----
    if (w == 0) {
        float p0 = pooled_s[l], p1 = pooled_s[l + 32];
        float px = p0 * W_pos[l * 2 + 0] + p1 * W_pos[(l + 32) * 2 + 0];
        float py = p0 * W_pos[l * 2 + 1] + p1 * W_pos[(l + 32) * 2 + 1];
        #pragma unroll
        for (int s = 16; s; s >>= 1) {
            px += __shfl_xor_sync(0xffffffffu, px, s);
            py += __shfl_xor_sync(0xffffffffu, py, s);
        }
        if (l == 0) {
            px += b_pos[0]; py += b_pos[1];
            out[i * 2 * (OBS + PRE) + (OBS + step) * 2 + 0] = px;
            out[i * 2 * (OBS + PRE) + (OBS + step) * 2 + 1] = py;
            pos_s[0] = px; pos_s[1] = py;
        }
    }
    __syncthreads();

    float px = pos_s[0], py = pos_s[1];
    if (t < HDIM) {
        // next-step u
        ((float*)g_u2[nbuf])[u_scalar_idx(i, t)] = px * W_rel[t] + py * W_rel[HDIM + t];
        // emb; stage h
        emb_s[t] = px * W_emb[t] + py * W_emb[HDIM + t] + b_emb[t];
        hv_s[t]  = g_h[i * HDIM + t];
    }
    __syncthreads();

    if (t < HDIM) {
        int c = t;
        float gir = b_ih[c], giz = b_ih[64 + c], gin = b_ih[128 + c];
        float ghr = b_hh[c], ghz = b_hh[64 + c], ghn = b_hh[128 + c];
        #pragma unroll 8
        for (int d = 0; d < HDIM; ++d) {
            float ed = emb_s[d], hd = hv_s[d];
            gir += ed * g_WihT[d * G3 + c];
            giz += ed * g_WihT[d * G3 + 64 + c];
            gin += ed * g_WihT[d * G3 + 128 + c];
            ghr += hd * g_WhhT[d * G3 + c];
            ghz += hd * g_WhhT[d * G3 + 64 + c];
            ghn += hd * g_WhhT[d * G3 + 128 + c];
        }
        float r = fsigmoid(gir + ghr);
        float z = fsigmoid(giz + ghz);
        float n = ftanh(gin + r * ghn);
        float hn = (1.0f - z) * n + z * hv_s[c];
        g_h[i * HDIM + c] = hn;
        hn_s[c] = hn;
    }
    __syncthreads();

    if (t < HDIM) {
        int c = t;
        float hp = b_pool[c];
        #pragma unroll 8
        for (int d = 0; d < HDIM; ++d)
            hp += hn_s[d] * W_pool[(HDIM + d) * HDIM + c];
        ((float*)g_hp2[nbuf])[hp_scalar_idx(i, c)] = hp;
    }
}

// ---------------------------------------------------------------------------
extern "C" void kernel_launch(void* const* d_in, const int* in_sizes, int n_in,
                              void* d_out, int out_size)
{
    const float* hidden = (const float*)d_in[0];
    const float* gt     = (const float*)d_in[1];
    const float* W_emb  = (const float*)d_in[2];
    const float* b_emb  = (const float*)d_in[3];
    const float* W_ih   = (const float*)d_in[4];
    const float* W_hh   = (const float*)d_in[5];
    const float* b_ih   = (const float*)d_in[6];
    const float* b_hh   = (const float*)d_in[7];
    const float* W_pos  = (const float*)d_in[8];
    const float* b_pos  = (const float*)d_in[9];
    const float* W_rel  = (const float*)d_in[10];
    const float* b_rel  = (const float*)d_in[11];
    const float* W_pool = (const float*)d_in[12];
    const float* b_pool = (const float*)d_in[13];
    float* out = (float*)d_out;

    init_kernel<<<BATCH + G3 + 32, 64>>>(hidden, gt, W_ih, W_hh, W_rel, W_pool, b_pool, out);
    for (int s = 0; s < PRE; ++s) {
        step_kernel<<<BATCH, 128>>>(b_rel, W_emb, b_emb, b_ih, b_hh,
                                    W_pos, b_pos, W_rel, W_pool, b_pool,
                                    out, s);
    }
}